// round 5
// baseline (speedup 1.0000x reference)
#include <cuda_runtime.h>

// Problem constants (fixed shapes from reference setup_inputs)
#define BATCH   4
#define NCH     4      // segmentation channels (class 0 = background)
#define NCLS    3      // foreground classes 1..3
#define NPTS    8192   // W*H = 64*128
#define CHUNK   256
#define MAXK    8192
#define RADIUS2 9.0f

// Spatial grid over kept points: 4m cells, 96x96 covering [-192, 192).
// Any pair with d <= 3m is within +-1 cell. A 4m cell holds at most 4 points
// pairwise > 3m apart (pigeonhole over 2x2m quadrants) -> capacity 4 is exact.
#define GC      96
#define GCELLS  (GC * GC)
#define GINV    0.25f
#define GORG    192.0f

// Dynamic shared layout (byte offsets):
//   float2         kept[MAXK]          @ 0        65536
//   unsigned short cellidx[GCELLS*4]   @ 65536    73728   (8B-aligned per cell)
//   int            counts[GCELLS]      @ 139264   36864
//   float          cx[CHUNK]           @ 176128    1024
//   float          cy[CHUNK]           @ 177152    1024
//   unsigned       col[CHUNK*8]        @ 178176    8192
static const int SMEM_BYTES = 186368;

__global__ __launch_bounds__(CHUNK, 1)
void radius_nms_kernel(const float* __restrict__ seg,
                       const float* __restrict__ lidar,
                       float* __restrict__ out) {
    extern __shared__ char smem_raw[];
    float2*         kept    = (float2*)smem_raw;
    unsigned short* cellidx = (unsigned short*)(smem_raw + 65536);
    int*            counts  = (int*)(smem_raw + 139264);
    float*          cx      = (float*)(smem_raw + 176128);
    float*          cy      = (float*)(smem_raw + 177152);
    unsigned*       col     = (unsigned*)(smem_raw + 178176);

    __shared__ unsigned keepbits[8];
    __shared__ int warpsum[8];
    __shared__ int kcount;

    const int blk  = blockIdx.x;          // 0..11
    const int b    = blk / NCLS;
    const int cls  = (blk % NCLS) + 1;    // foreground class 1..3
    const int t    = threadIdx.x;
    const int warp = t >> 5;
    const int lane = t & 31;

    const float* segb = seg + (size_t)b * NCH * NPTS;
    const float* lx   = lidar + (size_t)b * 5 * NPTS;   // lidar ch 0 = x
    const float* ly   = lx + NPTS;                       // ch 1 = y

    float* coord_out = out + (size_t)(b * NCLS + (cls - 1)) * NPTS * 2;
    float* keep_out  = out + (size_t)BATCH * NCLS * NPTS * 2
                           + (size_t)(b * NCLS + (cls - 1)) * NPTS;

    for (int i = t; i < GCELLS; i += CHUNK) counts[i] = 0;
    if (t == 0) kcount = 0;

    // ---- prefetch chunk 0 into registers
    float ps0 = segb[0 * NPTS + t];
    float ps1 = segb[1 * NPTS + t];
    float ps2 = segb[2 * NPTS + t];
    float ps3 = segb[3 * NPTS + t];
    float px  = lx[t];
    float py  = ly[t];

    __syncthreads();

    for (int base = 0; base < NPTS; base += CHUNK) {
        const int n = base + t;

        const float s0 = ps0, s1 = ps1, s2 = ps2, s3 = ps3;
        const float x = px, y = py;

        // ---- issue next chunk's loads early (hidden under serial phases)
        if (base + CHUNK < NPTS) {
            const int m = n + CHUNK;
            ps0 = segb[0 * NPTS + m];
            ps1 = segb[1 * NPTS + m];
            ps2 = segb[2 * NPTS + m];
            ps3 = segb[3 * NPTS + m];
            px  = lx[m];
            py  = ly[m];
        }

        // ---- per-pixel argmax class (first-max tie-break, like jnp.argmax)
        int   am = 0; float mv = s0;
        if (s1 > mv) { mv = s1; am = 1; }
        if (s2 > mv) { mv = s2; am = 2; }
        if (s3 > mv) { mv = s3; am = 3; }
        const bool valid = (am == cls);

        // ---- check against committed kept points via bucketed grid
        bool alive = valid;
        if (alive) {
            int gx = (int)floorf((x + GORG) * GINV);
            int gy = (int)floorf((y + GORG) * GINV);
            gx = min(max(gx, 0), GC - 1);
            gy = min(max(gy, 0), GC - 1);
            const int y0 = max(gy - 1, 0), y1 = min(gy + 1, GC - 1);
            const int x0 = max(gx - 1, 0), x1 = min(gx + 1, GC - 1);
            for (int yy = y0; yy <= y1 && alive; yy++) {
                for (int xx = x0; xx <= x1 && alive; xx++) {
                    const int cell = yy * GC + xx;
                    const int cnt = counts[cell];
                    if (cnt == 0) continue;
                    // one aligned 8B load -> 4 packed uint16 indices
                    uint2 s = *(const uint2*)&cellidx[cell * 4];
                    unsigned short id[4];
                    id[0] = (unsigned short)(s.x & 0xffff);
                    id[1] = (unsigned short)(s.x >> 16);
                    id[2] = (unsigned short)(s.y & 0xffff);
                    id[3] = (unsigned short)(s.y >> 16);
                    #pragma unroll
                    for (int c = 0; c < 4; c++) {
                        if (c < cnt) {
                            float2 k = kept[id[c]];
                            float ddx = x - k.x, ddy = y - k.y;
                            if (ddx * ddx + ddy * ddy <= RADIUS2) alive = false;
                        }
                    }
                }
            }
        }

        // ---- block exclusive scan of 'alive' -> candidates in index order
        unsigned bal = __ballot_sync(0xffffffffu, alive);
        if (lane == 0) warpsum[warp] = __popc(bal);
        __syncthreads();                                     // S1
        int woff = 0;
        #pragma unroll
        for (int w = 0; w < 8; w++) if (w < warp) woff += warpsum[w];
        int A = 0;
        #pragma unroll
        for (int w = 0; w < 8; w++) A += warpsum[w];
        const int pos = woff + __popc(bal & ((1u << lane) - 1u));
        if (alive) { cx[pos] = x; cy[pos] = y; }
        __syncthreads();                                     // S2

        // ---- conflict COLUMNS via ballots: col[i] bit t set iff
        //      t > i and d2(cand_t, cand_i) <= r2  (each warp owns its word)
        {
            const bool isc = (t < A);
            const float xt = isc ? cx[t] : 1.0e30f;
            const float yt = isc ? cy[t] : 1.0e30f;
            for (int i = 0; i < A; i++) {
                float dxx = xt - cx[i], dyy = yt - cy[i];
                bool c = (t > i) && (dxx * dxx + dyy * dyy <= RADIUS2);
                unsigned m = __ballot_sync(0xffffffffu, c);
                if (lane == 0) col[i * 8 + warp] = m;
            }
        }
        __syncthreads();                                     // S3

        // ---- serial greedy (thread 0), all bitset words in registers
        if (t == 0) {
            unsigned supp[8] = {0,0,0,0,0,0,0,0};
            unsigned kb[8]   = {0,0,0,0,0,0,0,0};
            #pragma unroll
            for (int w = 0; w < 8; w++) {
                const int lim = A - (w << 5);
                if (lim <= 0) break;
                const int nb = lim < 32 ? lim : 32;
                for (int k = 0; k < nb; k++) {
                    if (!((supp[w] >> k) & 1u)) {
                        kb[w] |= (1u << k);
                        const uint4* c4 = (const uint4*)&col[((w << 5) + k) * 8];
                        uint4 a = c4[0], bb = c4[1];
                        supp[0] |= a.x;  supp[1] |= a.y;
                        supp[2] |= a.z;  supp[3] |= a.w;
                        supp[4] |= bb.x; supp[5] |= bb.y;
                        supp[6] |= bb.z; supp[7] |= bb.w;
                    }
                }
            }
            #pragma unroll
            for (int w = 0; w < 8; w++) keepbits[w] = kb[w];
        }
        __syncthreads();                                     // S4

        // ---- resolve keep, append to kept[] + bucket insert, write outputs
        bool keepme = alive && ((keepbits[pos >> 5] >> (pos & 31)) & 1u);
        if (keepme) {
            int kpos = atomicAdd(&kcount, 1);
            kept[kpos] = make_float2(x, y);
            int gx = (int)floorf((x + GORG) * GINV);
            int gy = (int)floorf((y + GORG) * GINV);
            gx = min(max(gx, 0), GC - 1);
            gy = min(max(gy, 0), GC - 1);
            int cell = gy * GC + gx;
            int slot = atomicAdd(&counts[cell], 1);          // slot < 4 provably
            cellidx[cell * 4 + slot] = (unsigned short)kpos;
        }

        const float kf = keepme ? 1.0f : 0.0f;
        keep_out[n] = kf;
        reinterpret_cast<float2*>(coord_out)[n] = make_float2(x * kf, y * kf);

        __syncthreads();                                     // S5 (appends visible)
    }
}

extern "C" void kernel_launch(void* const* d_in, const int* in_sizes, int n_in,
                              void* d_out, int out_size) {
    (void)in_sizes; (void)n_in; (void)out_size;
    const float* seg   = (const float*)d_in[0];
    const float* lidar = (const float*)d_in[1];
    float* out = (float*)d_out;

    cudaFuncSetAttribute(radius_nms_kernel,
                         cudaFuncAttributeMaxDynamicSharedMemorySize, SMEM_BYTES);
    radius_nms_kernel<<<BATCH * NCLS, CHUNK, SMEM_BYTES>>>(seg, lidar, out);
}

// round 6
// speedup vs baseline: 1.4579x; 1.4579x over previous
#include <cuda_runtime.h>

// Problem constants (fixed shapes from reference setup_inputs)
#define BATCH   4
#define NCH     4      // segmentation channels (class 0 = background)
#define NCLS    3      // foreground classes 1..3
#define NPTS    8192   // W*H = 64*128
#define CHUNK   256
#define MAXK    8192
#define RADIUS2 9.0f

// Spatial grid over kept points: 4m cells, 96x96 interior covering [-192,192),
// padded to 98x98 (1-cell border, always empty) so the 3x3 probe needs no
// bounds checks. A 4m cell holds at most 4 points pairwise > 3m apart
// (pigeonhole over 2x2m quadrants) -> slot capacity 4 is provably exact.
#define GC      96
#define GP      98
#define GPCELLS (GP * GP)
#define GINV    0.25f
#define GORG    192.0f

// Dynamic shared layout (byte offsets):
//   float2         kept[MAXK]          @ 0        65536
//   unsigned short cellidx[GPCELLS*4]  @ 65536    76832  (init 0xFFFF sentinel)
//   int            counts[GPCELLS]     @ 142368   38416  (insert slots only)
//   float          cx[CHUNK]           @ 180784    1024
//   float          cy[CHUNK]           @ 181808    1024
//   unsigned       col[CHUNK*8]        @ 182832    8192  (16B-aligned)
static const int SMEM_BYTES = 191024;

__global__ __launch_bounds__(CHUNK, 1)
void radius_nms_kernel(const float* __restrict__ seg,
                       const float* __restrict__ lidar,
                       float* __restrict__ out) {
    extern __shared__ char smem_raw[];
    float2*         kept    = (float2*)smem_raw;
    unsigned short* cellidx = (unsigned short*)(smem_raw + 65536);
    int*            counts  = (int*)(smem_raw + 142368);
    float*          cx      = (float*)(smem_raw + 180784);
    float*          cy      = (float*)(smem_raw + 181808);
    unsigned*       col     = (unsigned*)(smem_raw + 182832);

    __shared__ unsigned keepbits[8];
    __shared__ int warpsum[8];
    __shared__ int kcount;

    const int blk  = blockIdx.x;          // 0..11
    const int b    = blk / NCLS;
    const int cls  = (blk % NCLS) + 1;    // foreground class 1..3
    const int t    = threadIdx.x;
    const int warp = t >> 5;
    const int lane = t & 31;

    const float* segb = seg + (size_t)b * NCH * NPTS;
    const float* lx   = lidar + (size_t)b * 5 * NPTS;   // lidar ch 0 = x
    const float* ly   = lx + NPTS;                       // ch 1 = y

    float* coord_out = out + (size_t)(b * NCLS + (cls - 1)) * NPTS * 2;
    float* keep_out  = out + (size_t)BATCH * NCLS * NPTS * 2
                           + (size_t)(b * NCLS + (cls - 1)) * NPTS;

    // init: sentinel indices, zero insert counters
    {
        unsigned* ci32 = (unsigned*)cellidx;             // 2 slots per word
        for (int i = t; i < GPCELLS * 2; i += CHUNK) ci32[i] = 0xffffffffu;
        for (int i = t; i < GPCELLS; i += CHUNK) counts[i] = 0;
        if (t == 0) kcount = 0;
    }

    // prefetch chunk 0 into registers
    float ps0 = segb[0 * NPTS + t];
    float ps1 = segb[1 * NPTS + t];
    float ps2 = segb[2 * NPTS + t];
    float ps3 = segb[3 * NPTS + t];
    float px  = lx[t];
    float py  = ly[t];

    __syncthreads();

    for (int base = 0; base < NPTS; base += CHUNK) {
        const int n = base + t;

        const float s0 = ps0, s1 = ps1, s2 = ps2, s3 = ps3;
        const float x = px, y = py;

        if (base + CHUNK < NPTS) {                        // prefetch next chunk
            const int m = n + CHUNK;
            ps0 = segb[0 * NPTS + m];
            ps1 = segb[1 * NPTS + m];
            ps2 = segb[2 * NPTS + m];
            ps3 = segb[3 * NPTS + m];
            px  = lx[m];
            py  = ly[m];
        }

        // ---- per-pixel argmax class (first-max tie-break, like jnp.argmax)
        int   am = 0; float mv = s0;
        if (s1 > mv) { mv = s1; am = 1; }
        if (s2 > mv) { mv = s2; am = 2; }
        if (s3 > mv) { mv = s3; am = 3; }
        const bool valid = (am == cls);

        // ---- grid cell (interior coords clamp into [0,95])
        int gx = (int)floorf((x + GORG) * GINV);
        int gy = (int)floorf((y + GORG) * GINV);
        gx = min(max(gx, 0), GC - 1);
        gy = min(max(gy, 0), GC - 1);
        const int ccell = (gy + 1) * GP + (gx + 1);       // padded index

        // ---- BRANCHLESS probe: 3x3 cells x 4 slots, sentinel-gated.
        //      All loads unconditional (idx masked in-bounds) -> full MLP.
        bool sup = false;
        #pragma unroll
        for (int dy = -1; dy <= 1; dy++) {
            #pragma unroll
            for (int dx = -1; dx <= 1; dx++) {
                const int cell = ccell + dy * GP + dx;
                uint2 s = *(const uint2*)&cellidx[cell * 4];
                const unsigned id0 = s.x & 0xffffu, id1 = s.x >> 16;
                const unsigned id2 = s.y & 0xffffu, id3 = s.y >> 16;
                float2 k0 = kept[id0 & 0x1fffu];
                float2 k1 = kept[id1 & 0x1fffu];
                float2 k2 = kept[id2 & 0x1fffu];
                float2 k3 = kept[id3 & 0x1fffu];
                float d0 = (x-k0.x)*(x-k0.x) + (y-k0.y)*(y-k0.y);
                float d1 = (x-k1.x)*(x-k1.x) + (y-k1.y)*(y-k1.y);
                float d2 = (x-k2.x)*(x-k2.x) + (y-k2.y)*(y-k2.y);
                float d3 = (x-k3.x)*(x-k3.x) + (y-k3.y)*(y-k3.y);
                sup |= (id0 != 0xffffu) & (d0 <= RADIUS2);
                sup |= (id1 != 0xffffu) & (d1 <= RADIUS2);
                sup |= (id2 != 0xffffu) & (d2 <= RADIUS2);
                sup |= (id3 != 0xffffu) & (d3 <= RADIUS2);
            }
        }
        const bool alive = valid && !sup;

        // ---- block exclusive scan of 'alive' -> candidates in index order
        unsigned bal = __ballot_sync(0xffffffffu, alive);
        if (lane == 0) warpsum[warp] = __popc(bal);
        __syncthreads();                                     // S1
        int woff = 0;
        #pragma unroll
        for (int w = 0; w < 8; w++) if (w < warp) woff += warpsum[w];
        int A = 0;
        #pragma unroll
        for (int w = 0; w < 8; w++) A += warpsum[w];
        const int pos = woff + __popc(bal & ((1u << lane) - 1u));
        if (alive) { cx[pos] = x; cy[pos] = y; }
        __syncthreads();                                     // S2

        // ---- conflict COLUMNS via ballots: col[i] bit t set iff
        //      t > i and d2(cand_t, cand_i) <= r2  (each warp owns its word)
        {
            const bool isc = (t < A);
            const float xt = isc ? cx[t] : 1.0e30f;
            const float yt = isc ? cy[t] : 1.0e30f;
            #pragma unroll 2
            for (int i = 0; i < A; i++) {
                float dxx = xt - cx[i], dyy = yt - cy[i];
                bool c = (t > i) && (dxx * dxx + dyy * dyy <= RADIUS2);
                unsigned m = __ballot_sync(0xffffffffu, c);
                if (lane == 0) col[i * 8 + warp] = m;
            }
        }
        __syncthreads();                                     // S3

        // ---- serial greedy (thread 0): BRANCHLESS, loads independent of
        //      the supp chain (mask-select), all bitset words in registers.
        if (t == 0) {
            unsigned supp[8] = {0,0,0,0,0,0,0,0};
            unsigned kb[8]   = {0,0,0,0,0,0,0,0};
            #pragma unroll
            for (int w = 0; w < 8; w++) {
                const int lim = A - (w << 5);
                if (lim <= 0) break;
                const int nb = lim < 32 ? lim : 32;
                for (int k = 0; k < nb; k++) {
                    const uint4* c4 = (const uint4*)&col[((w << 5) + k) * 8];
                    uint4 a = c4[0], bb = c4[1];
                    unsigned kbit = (~supp[w] >> k) & 1u;
                    kb[w] |= kbit << k;
                    unsigned msk = (unsigned)(0u - kbit);
                    supp[0] |= msk & a.x;  supp[1] |= msk & a.y;
                    supp[2] |= msk & a.z;  supp[3] |= msk & a.w;
                    supp[4] |= msk & bb.x; supp[5] |= msk & bb.y;
                    supp[6] |= msk & bb.z; supp[7] |= msk & bb.w;
                }
            }
            #pragma unroll
            for (int w = 0; w < 8; w++) keepbits[w] = kb[w];
        }
        __syncthreads();                                     // S4

        // ---- resolve keep, append to kept[] + cell insert, write outputs
        bool keepme = alive && ((keepbits[pos >> 5] >> (pos & 31)) & 1u);
        if (keepme) {
            int kpos = atomicAdd(&kcount, 1);
            kept[kpos] = make_float2(x, y);
            int slot = atomicAdd(&counts[ccell], 1);         // slot < 4 provably
            cellidx[ccell * 4 + slot] = (unsigned short)kpos;
        }

        const float kf = keepme ? 1.0f : 0.0f;
        keep_out[n] = kf;
        reinterpret_cast<float2*>(coord_out)[n] = make_float2(x * kf, y * kf);

        __syncthreads();                                     // S5 (appends visible)
    }
}

extern "C" void kernel_launch(void* const* d_in, const int* in_sizes, int n_in,
                              void* d_out, int out_size) {
    (void)in_sizes; (void)n_in; (void)out_size;
    const float* seg   = (const float*)d_in[0];
    const float* lidar = (const float*)d_in[1];
    float* out = (float*)d_out;

    cudaFuncSetAttribute(radius_nms_kernel,
                         cudaFuncAttributeMaxDynamicSharedMemorySize, SMEM_BYTES);
    radius_nms_kernel<<<BATCH * NCLS, CHUNK, SMEM_BYTES>>>(seg, lidar, out);
}